// round 13
// baseline (speedup 1.0000x reference)
#include <cuda_runtime.h>
#include <math.h>
#include <stdint.h>

#define D 128
#define MAXN 50000
#define MAXE 800000

// ---- persistent scratch (no allocation allowed) ----
__device__ float g_h[MAXN * D];     // current node features
__device__ float g_tmp[MAXN * D];   // h @ W (optionally pre-scaled by dinv)
__device__ int   g_deg[MAXN];
__device__ float g_dinv[MAXN];
__device__ int   g_rowptr[MAXN + 1];
__device__ int   g_cursor[MAXN];
__device__ int   g_csr[MAXE];       // src node per CSR slot (grouped by dst)
__device__ int   g_ei64;            // 1 if edge_index is int64, 0 if int32
__device__ int   g_b64;             // 1 if batch is int64, 0 if int32

__device__ __forceinline__ int idx_at(const void* p, long long i, int is64) {
    return is64 ? (int)((const long long*)p)[i] : ((const int*)p)[i];
}

// ---------------------------------------------------------------------------
// zero degree array + init dtype flags (fused)
__global__ void k_zero_deg(int n) {
    int i = blockIdx.x * blockDim.x + threadIdx.x;
    if (i < n) g_deg[i] = 0;
    if (i == 0) { g_ei64 = 1; g_b64 = 1; }
}

// Parallel dtype detection: interpret first cnt/2 entries as int64; any value
// outside [0, range) => buffer is int32 (atomicAnd clears flag).
__global__ void k_detect(const void* __restrict__ buf, int cnt, int range, int which) {
    const long long* p = (const long long*)buf;
    int S = cnt / 2; if (S > 8192) S = 8192;
    int bad = 0;
    for (int i = blockIdx.x * blockDim.x + threadIdx.x; i < S;
         i += gridDim.x * blockDim.x) {
        long long v = p[i];
        if (v < 0 || v >= range) bad = 1;
    }
    if (__syncthreads_or(bad)) {
        if (threadIdx.x == 0) {
            if (which == 0) atomicAnd(&g_ei64, 0);
            else            atomicAnd(&g_b64, 0);
        }
    }
}

__global__ void k_count(const void* __restrict__ ei, int E, int N) {
    int e = blockIdx.x * blockDim.x + threadIdx.x;
    if (e < E) {
        int d = idx_at(ei, (long long)E + e, g_ei64);
        if (d >= 0 && d < N) atomicAdd(&g_deg[d], 1);
    }
}

// single-block scan over degrees -> rowptr, cursor (+ fused dinv)
__global__ void k_scan(int n, int E) {
    __shared__ int part[1024];
    int t = threadIdx.x;
    int chunk = (n + 1023) >> 10;
    int base = t * chunk;
    int s = 0;
    for (int i = 0; i < chunk; i++) {
        int idx = base + i;
        if (idx < n) s += g_deg[idx];
    }
    part[t] = s;
    __syncthreads();
    for (int off = 1; off < 1024; off <<= 1) {
        int v = 0;
        if (t >= off) v = part[t - off];
        __syncthreads();
        part[t] += v;
        __syncthreads();
    }
    int run = (t > 0) ? part[t - 1] : 0;
    for (int i = 0; i < chunk; i++) {
        int idx = base + i;
        if (idx < n) {
            int dg = g_deg[idx];
            g_rowptr[idx] = run;
            g_cursor[idx] = run;
            g_dinv[idx] = rsqrtf((float)(dg + 1));  // +1 self loop
            run += dg;
        }
    }
    if (t == 0) g_rowptr[n] = part[1023];
}

__global__ void k_scatter(const void* __restrict__ ei, int E, int N) {
    int e = blockIdx.x * blockDim.x + threadIdx.x;
    if (e < E) {
        int s = idx_at(ei, e, g_ei64);
        int d = idx_at(ei, (long long)E + e, g_ei64);
        if (s >= 0 && s < N && d >= 0 && d < N) {
            int p = atomicAdd(&g_cursor[d], 1);
            if (p >= 0 && p < E) g_csr[p] = s;
        }
    }
}

// ---------------------------------------------------------------------------
// g_tmp = (A @ Wl) [* dinv[row] if scale]   (A = X if useX else g_h)
// 128x128 output tile per block, 256 threads, 8x8 per-thread microtile, BK=32
__global__ void __launch_bounds__(256) k_gemm(const float* __restrict__ X,
                                              const float* __restrict__ Wl,
                                              int M, int useX, int scale) {
    const float* A = useX ? X : g_h;
    __shared__ float sa[32][128];   // [k][m] (A transposed)
    __shared__ float sbuf[32][128]; // [k][n]
    int tid = threadIdx.x;
    int m0 = blockIdx.x * 128;
    int tx = tid & 15, ty = tid >> 4;

    float acc[8][8];
#pragma unroll
    for (int i = 0; i < 8; i++)
#pragma unroll
        for (int j = 0; j < 8; j++) acc[i][j] = 0.f;

    for (int kt = 0; kt < 4; kt++) {
        // W tile: 32 rows x 128 cols = 1024 float4
#pragma unroll
        for (int i = 0; i < 4; i++) {
            int lin = tid + 256 * i;
            int r = lin >> 5;     // k-row within tile
            int c4 = lin & 31;    // float4 column
            float4 v = ((const float4*)(Wl + (size_t)(kt * 32 + r) * 128))[c4];
            ((float4*)&sbuf[r][0])[c4] = v;
        }
        // A tile (transposed in smem): 128 rows x 32 k = 1024 float4
#pragma unroll
        for (int i = 0; i < 4; i++) {
            int lin = tid + 256 * i;
            int r = lin >> 3;     // m-row in tile
            int k4 = lin & 7;     // float4 within 32-k slab
            float4 v = make_float4(0.f, 0.f, 0.f, 0.f);
            int row = m0 + r;
            if (row < M) v = ((const float4*)(A + (size_t)row * 128 + kt * 32))[k4];
            int k = k4 * 4;
            sa[k][r] = v.x; sa[k + 1][r] = v.y; sa[k + 2][r] = v.z; sa[k + 3][r] = v.w;
        }
        __syncthreads();
#pragma unroll
        for (int k = 0; k < 32; k++) {
            float4 a0 = *((const float4*)&sa[k][ty * 8]);
            float4 a1 = *((const float4*)&sa[k][ty * 8 + 4]);
            float4 b0 = *((const float4*)&sbuf[k][tx * 8]);
            float4 b1 = *((const float4*)&sbuf[k][tx * 8 + 4]);
            float av[8] = {a0.x, a0.y, a0.z, a0.w, a1.x, a1.y, a1.z, a1.w};
            float bv[8] = {b0.x, b0.y, b0.z, b0.w, b1.x, b1.y, b1.z, b1.w};
#pragma unroll
            for (int i = 0; i < 8; i++)
#pragma unroll
                for (int j = 0; j < 8; j++) acc[i][j] += av[i] * bv[j];
        }
        __syncthreads();
    }
#pragma unroll
    for (int i = 0; i < 8; i++) {
        int row = m0 + ty * 8 + i;
        if (row < M) {
            float dv = scale ? g_dinv[row] : 1.0f;
            float4 o0 = make_float4(acc[i][0] * dv, acc[i][1] * dv,
                                    acc[i][2] * dv, acc[i][3] * dv);
            float4 o1 = make_float4(acc[i][4] * dv, acc[i][5] * dv,
                                    acc[i][6] * dv, acc[i][7] * dv);
            ((float4*)(g_tmp + (size_t)row * 128))[tx * 2] = o0;
            ((float4*)(g_tmp + (size_t)row * 128))[tx * 2 + 1] = o1;
        }
    }
}

// ---------------------------------------------------------------------------
// gather aggregation. If prescaled: tmp already holds (hW)*dinv, inner loop is
// pure adds. Else (layer 1, tmp unscaled): multiply each message by dinv[s].
// g_h[n] = relu( acc * dinv[n] + bias ), one warp per node, float4 per lane.
__global__ void __launch_bounds__(256) k_agg(const float* __restrict__ bias,
                                             int N, int E, int prescaled) {
    int wid = blockIdx.x * (blockDim.x >> 5) + (threadIdx.x >> 5);
    int lane = threadIdx.x & 31;
    if (wid >= N) return;
    float dn = g_dinv[wid];
    float4 sv = ((const float4*)(g_tmp + (size_t)wid * D))[lane];
    float sf = prescaled ? 1.0f : dn;      // self term scale
    float4 acc = make_float4(sv.x * sf, sv.y * sf, sv.z * sf, sv.w * sf);
    int beg = g_rowptr[wid], end = g_rowptr[wid + 1];
    if (beg < 0) beg = 0;
    if (end > E) end = E;
    if (prescaled) {
#pragma unroll 4
        for (int e = beg; e < end; e++) {
            int s = g_csr[e];
            float4 u = ((const float4*)(g_tmp + (size_t)s * D))[lane];
            acc.x += u.x; acc.y += u.y; acc.z += u.z; acc.w += u.w;
        }
    } else {
#pragma unroll 4
        for (int e = beg; e < end; e++) {
            int s = g_csr[e];
            float ds = g_dinv[s];
            float4 u = ((const float4*)(g_tmp + (size_t)s * D))[lane];
            acc.x = fmaf(u.x, ds, acc.x); acc.y = fmaf(u.y, ds, acc.y);
            acc.z = fmaf(u.z, ds, acc.z); acc.w = fmaf(u.w, ds, acc.w);
        }
    }
    float4 bb = ((const float4*)bias)[lane];
    float4 r;
    r.x = fmaxf(fmaf(acc.x, dn, bb.x), 0.f);
    r.y = fmaxf(fmaf(acc.y, dn, bb.y), 0.f);
    r.z = fmaxf(fmaf(acc.z, dn, bb.z), 0.f);
    r.w = fmaxf(fmaf(acc.w, dn, bb.w), 0.f);
    ((float4*)(g_h + (size_t)wid * D))[lane] = r;
}

// ---------------------------------------------------------------------------
// mean pool per graph + linear head + log_softmax. one block per graph.
__global__ void k_pool(const void* __restrict__ batch,
                       const float* __restrict__ lin_w,
                       const float* __restrict__ lin_b,
                       float* hG_out, float* log_out,
                       int N, int nc) {
    int g = blockIdx.x, t = threadIdx.x;
    __shared__ int bounds[2];
    __shared__ float sh[D];
    __shared__ float sl[32];
    int is64 = g_b64;
    if (t == 0) {
        int lo = 0, hi = N;
        while (lo < hi) { int mid = (lo + hi) >> 1; if (idx_at(batch, mid, is64) < g) lo = mid + 1; else hi = mid; }
        bounds[0] = lo;
        hi = N;
        while (lo < hi) { int mid = (lo + hi) >> 1; if (idx_at(batch, mid, is64) <= g) lo = mid + 1; else hi = mid; }
        bounds[1] = lo;
    }
    __syncthreads();
    int beg = bounds[0], end = bounds[1];
    float sum = 0.f;
    for (int i = beg; i < end; i++) sum += g_h[(size_t)i * D + t];
    int c = end - beg;
    float cnt = (float)(c > 1 ? c : 1);
    float m = sum / cnt;
    if (hG_out) hG_out[(size_t)g * D + t] = m;
    sh[t] = m;
    __syncthreads();
    if (log_out) {
        if (t < nc) {
            float acc = lin_b[t];
            for (int k = 0; k < D; k++) acc += sh[k] * lin_w[k * nc + t];
            sl[t] = acc;
        }
        __syncthreads();
        if (t == 0) {
            float mx = -1e30f;
            for (int j = 0; j < nc; j++) mx = fmaxf(mx, sl[j]);
            float se = 0.f;
            for (int j = 0; j < nc; j++) se += expf(sl[j] - mx);
            float lse = mx + logf(se);
            for (int j = 0; j < nc; j++) log_out[(size_t)g * nc + j] = sl[j] - lse;
        }
    }
}

// ---------------------------------------------------------------------------
extern "C" void kernel_launch(void* const* d_in, const int* in_sizes, int n_in,
                              void* d_out, int out_size) {
    // Identify inputs by (distinct) element counts; fall back to position.
    const float* x = (const float*)d_in[0];
    const float* W = (const float*)d_in[1];
    const float* b = (const float*)d_in[2];
    const float* lin_w = (const float*)d_in[3];
    const float* lin_b = (const float*)d_in[4];
    const void* ei = d_in[5];
    const void* batch = d_in[6];
    int sz_x = in_sizes[0], sz_W = in_sizes[1], sz_lb = in_sizes[4],
        sz_ei = in_sizes[5], sz_batch = in_sizes[6];
    for (int i = 0; i < n_in; i++) {
        int s = in_sizes[i];
        switch (s) {
            case 6400000: x = (const float*)d_in[i]; sz_x = s; break;       // N*D
            case 49152:   W = (const float*)d_in[i]; sz_W = s; break;       // L*D*D
            case 384:     b = (const float*)d_in[i]; break;                 // L*D
            case 1280:    lin_w = (const float*)d_in[i]; break;             // D*nc
            case 10:      lin_b = (const float*)d_in[i]; sz_lb = s; break;  // nc
            case 1600000: ei = d_in[i]; sz_ei = s; break;                   // 2*E
            case 50000:   batch = d_in[i]; sz_batch = s; break;             // N
            default: break;
        }
    }

    int N = sz_x / D;
    int E = sz_ei / 2;
    int L = sz_W / (D * D);
    int nc = sz_lb;

    float* out = (float*)d_out;
    float* hG_out = 0;
    float* log_out = 0;
    int G = 0;
    if (out_size % (D + nc) == 0) {     // concatenated (hG, log_softmax)
        G = out_size / (D + nc);
        hG_out = out;
        log_out = out + (size_t)G * D;
    } else if (out_size % D == 0) {     // hG only
        G = out_size / D;
        hG_out = out;
    } else {                            // logits only
        G = out_size / nc;
        log_out = out;
    }

    // one-time host-side infra (streams/events are not device memory)
    static cudaStream_t s_pre = 0;
    static cudaEvent_t ev_fork = 0, ev_join = 0;
    if (!s_pre) {
        cudaStreamCreateWithFlags(&s_pre, cudaStreamNonBlocking);
        cudaEventCreateWithFlags(&ev_fork, cudaEventDisableTiming);
        cudaEventCreateWithFlags(&ev_join, cudaEventDisableTiming);
    }

    int tE = (E + 255) / 256;
    int tN = (N + 255) / 256;
    int gemm_blocks = (N + 127) / 128;
    int agg_blocks = (N + 7) / 8;       // 8 warps/block, warp per node

    // ---- fork: CSR build on side stream, layer-1 GEMM on main stream ----
    cudaEventRecord(ev_fork, 0);
    cudaStreamWaitEvent(s_pre, ev_fork, 0);

    k_gemm<<<gemm_blocks, 256>>>(x, W, N, 1, 0);            // main: x @ W0 (unscaled)

    k_zero_deg<<<tN, 256, 0, s_pre>>>(N);                   // side: CSR chain
    k_detect<<<16, 256, 0, s_pre>>>(ei, sz_ei, N, 0);
    k_detect<<<16, 256, 0, s_pre>>>(batch, sz_batch, G, 1);
    k_count<<<tE, 256, 0, s_pre>>>(ei, E, N);
    k_scan<<<1, 1024, 0, s_pre>>>(N, E);
    k_scatter<<<tE, 256, 0, s_pre>>>(ei, E, N);

    cudaEventRecord(ev_join, s_pre);
    cudaStreamWaitEvent(0, ev_join, 0);

    // ---- join: layer 1 agg applies dinv per-edge; layers 2+ pre-scale ----
    k_agg<<<agg_blocks, 256>>>(b, N, E, 0);
    for (int l = 1; l < L; l++) {
        k_gemm<<<gemm_blocks, 256>>>(x, W + (size_t)l * D * D, N, 0, 1);
        k_agg<<<agg_blocks, 256>>>(b + (size_t)l * D, N, E, 1);
    }
    k_pool<<<G, D>>>(batch, lin_w, lin_b, hG_out, log_out, N, nc);
}

// round 14
// speedup vs baseline: 1.0835x; 1.0835x over previous
#include <cuda_runtime.h>
#include <cuda_fp16.h>
#include <math.h>
#include <stdint.h>

#define D 128
#define MAXN 50000
#define MAXE 800000

// ---- persistent scratch (no allocation allowed) ----
__device__ float g_h[MAXN * D];                   // node features (fp32)
__device__ __align__(16) __half g_tmp[MAXN * D];  // (h @ W) * dinv, fp16
__device__ int   g_deg[MAXN];
__device__ float g_dinv[MAXN];
__device__ int   g_rowptr[MAXN + 1];
__device__ int   g_cursor[MAXN];
__device__ int   g_csr[MAXE];       // src node per CSR slot (grouped by dst)
__device__ int   g_ei64;            // 1 if edge_index is int64, 0 if int32
__device__ int   g_b64;             // 1 if batch is int64, 0 if int32

__device__ __forceinline__ int idx_at(const void* p, long long i, int is64) {
    return is64 ? (int)((const long long*)p)[i] : ((const int*)p)[i];
}

// ---------------------------------------------------------------------------
// zero degree array + init dtype flags (fused)
__global__ void k_zero_deg(int n) {
    int i = blockIdx.x * blockDim.x + threadIdx.x;
    if (i < n) g_deg[i] = 0;
    if (i == 0) { g_ei64 = 1; g_b64 = 1; }
}

// Merged dtype detection: blocks 0-15 scan edge_index, 16-31 scan batch.
// Interpret first cnt/2 entries as int64; any value outside [0, range)
// => buffer is int32 (atomicAnd clears flag). Stays within cnt*4 bytes.
__global__ void k_detect2(const void* __restrict__ ei, int eicnt, int N,
                          const void* __restrict__ bt, int btcnt, int G) {
    int which = blockIdx.x >> 4;                 // 0: ei, 1: batch
    const long long* p = (const long long*)(which ? bt : ei);
    int cnt = which ? btcnt : eicnt;
    int range = which ? G : N;
    int S = cnt / 2; if (S > 8192) S = 8192;
    int bad = 0;
    for (int i = (blockIdx.x & 15) * blockDim.x + threadIdx.x; i < S;
         i += 16 * blockDim.x) {
        long long v = p[i];
        if (v < 0 || v >= range) bad = 1;
    }
    if (__syncthreads_or(bad)) {
        if (threadIdx.x == 0) {
            if (which == 0) atomicAnd(&g_ei64, 0);
            else            atomicAnd(&g_b64, 0);
        }
    }
}

__global__ void k_count(const void* __restrict__ ei, int E, int N) {
    int e = blockIdx.x * blockDim.x + threadIdx.x;
    if (e < E) {
        int d = idx_at(ei, (long long)E + e, g_ei64);
        if (d >= 0 && d < N) atomicAdd(&g_deg[d], 1);
    }
}

// single-block scan over degrees -> rowptr, cursor (+ fused dinv)
__global__ void k_scan(int n, int E) {
    __shared__ int part[1024];
    int t = threadIdx.x;
    int chunk = (n + 1023) >> 10;
    int base = t * chunk;
    int s = 0;
    for (int i = 0; i < chunk; i++) {
        int idx = base + i;
        if (idx < n) s += g_deg[idx];
    }
    part[t] = s;
    __syncthreads();
    for (int off = 1; off < 1024; off <<= 1) {
        int v = 0;
        if (t >= off) v = part[t - off];
        __syncthreads();
        part[t] += v;
        __syncthreads();
    }
    int run = (t > 0) ? part[t - 1] : 0;
    for (int i = 0; i < chunk; i++) {
        int idx = base + i;
        if (idx < n) {
            int dg = g_deg[idx];
            g_rowptr[idx] = run;
            g_cursor[idx] = run;
            g_dinv[idx] = rsqrtf((float)(dg + 1));  // +1 self loop
            run += dg;
        }
    }
    if (t == 0) g_rowptr[n] = part[1023];
}

__global__ void k_scatter(const void* __restrict__ ei, int E, int N) {
    int e = blockIdx.x * blockDim.x + threadIdx.x;
    if (e < E) {
        int s = idx_at(ei, e, g_ei64);
        int d = idx_at(ei, (long long)E + e, g_ei64);
        if (s >= 0 && s < N && d >= 0 && d < N) {
            int p = atomicAdd(&g_cursor[d], 1);
            if (p >= 0 && p < E) g_csr[p] = s;
        }
    }
}

// ---------------------------------------------------------------------------
// g_tmp = half((A @ Wl) * dinv[row])   (A = X if useX else g_h)
// 128x128 output tile per block, 256 threads, 8x8 per-thread microtile, BK=32
__global__ void __launch_bounds__(256) k_gemm(const float* __restrict__ X,
                                              const float* __restrict__ Wl,
                                              int M, int useX) {
    const float* A = useX ? X : g_h;
    __shared__ float sa[32][128];   // [k][m] (A transposed)
    __shared__ float sbuf[32][128]; // [k][n]
    int tid = threadIdx.x;
    int m0 = blockIdx.x * 128;
    int tx = tid & 15, ty = tid >> 4;

    float acc[8][8];
#pragma unroll
    for (int i = 0; i < 8; i++)
#pragma unroll
        for (int j = 0; j < 8; j++) acc[i][j] = 0.f;

    for (int kt = 0; kt < 4; kt++) {
        // W tile: 32 rows x 128 cols = 1024 float4
#pragma unroll
        for (int i = 0; i < 4; i++) {
            int lin = tid + 256 * i;
            int r = lin >> 5;     // k-row within tile
            int c4 = lin & 31;    // float4 column
            float4 v = ((const float4*)(Wl + (size_t)(kt * 32 + r) * 128))[c4];
            ((float4*)&sbuf[r][0])[c4] = v;
        }
        // A tile (transposed in smem): 128 rows x 32 k = 1024 float4
#pragma unroll
        for (int i = 0; i < 4; i++) {
            int lin = tid + 256 * i;
            int r = lin >> 3;     // m-row in tile
            int k4 = lin & 7;     // float4 within 32-k slab
            float4 v = make_float4(0.f, 0.f, 0.f, 0.f);
            int row = m0 + r;
            if (row < M) v = ((const float4*)(A + (size_t)row * 128 + kt * 32))[k4];
            int k = k4 * 4;
            sa[k][r] = v.x; sa[k + 1][r] = v.y; sa[k + 2][r] = v.z; sa[k + 3][r] = v.w;
        }
        __syncthreads();
#pragma unroll
        for (int k = 0; k < 32; k++) {
            float4 a0 = *((const float4*)&sa[k][ty * 8]);
            float4 a1 = *((const float4*)&sa[k][ty * 8 + 4]);
            float4 b0 = *((const float4*)&sbuf[k][tx * 8]);
            float4 b1 = *((const float4*)&sbuf[k][tx * 8 + 4]);
            float av[8] = {a0.x, a0.y, a0.z, a0.w, a1.x, a1.y, a1.z, a1.w};
            float bv[8] = {b0.x, b0.y, b0.z, b0.w, b1.x, b1.y, b1.z, b1.w};
#pragma unroll
            for (int i = 0; i < 8; i++)
#pragma unroll
                for (int j = 0; j < 8; j++) acc[i][j] += av[i] * bv[j];
        }
        __syncthreads();
    }
    // epilogue: scale by dinv, convert to half2, one 16B store per row
#pragma unroll
    for (int i = 0; i < 8; i++) {
        int row = m0 + ty * 8 + i;
        if (row < M) {
            float dv = g_dinv[row];
            __half2 p0 = __floats2half2_rn(acc[i][0] * dv, acc[i][1] * dv);
            __half2 p1 = __floats2half2_rn(acc[i][2] * dv, acc[i][3] * dv);
            __half2 p2 = __floats2half2_rn(acc[i][4] * dv, acc[i][5] * dv);
            __half2 p3 = __floats2half2_rn(acc[i][6] * dv, acc[i][7] * dv);
            uint4 pk = make_uint4(*(uint32_t*)&p0, *(uint32_t*)&p1,
                                  *(uint32_t*)&p2, *(uint32_t*)&p3);
            ((uint4*)(g_tmp + (size_t)row * D))[tx] = pk;
        }
    }
}

// ---------------------------------------------------------------------------
// gather aggregation, fp16 messages (half L2 traffic), fp32 accumulate:
// g_h[n] = relu( (tmp'[n] + sum_{s in in(n)} tmp'[s]) * dinv[n] + bias )
// one warp per node; lane covers 4 features (uint2 = 4 halves = 8 B)
__global__ void __launch_bounds__(256) k_agg(const float* __restrict__ bias, int N, int E) {
    int wid = blockIdx.x * (blockDim.x >> 5) + (threadIdx.x >> 5);
    int lane = threadIdx.x & 31;
    if (wid >= N) return;
    float dn = g_dinv[wid];
    uint2 sv = ((const uint2*)(g_tmp + (size_t)wid * D))[lane];  // self term
    float2 f0 = __half22float2(*(__half2*)&sv.x);
    float2 f1 = __half22float2(*(__half2*)&sv.y);
    float4 acc = make_float4(f0.x, f0.y, f1.x, f1.y);
    int beg = g_rowptr[wid], end = g_rowptr[wid + 1];
    if (beg < 0) beg = 0;
    if (end > E) end = E;
#pragma unroll 4
    for (int e = beg; e < end; e++) {
        int s = g_csr[e];
        uint2 uv = ((const uint2*)(g_tmp + (size_t)s * D))[lane];
        float2 u0 = __half22float2(*(__half2*)&uv.x);
        float2 u1 = __half22float2(*(__half2*)&uv.y);
        acc.x += u0.x; acc.y += u0.y; acc.z += u1.x; acc.w += u1.y;
    }
    float4 bb = ((const float4*)bias)[lane];
    float4 r;
    r.x = fmaxf(fmaf(acc.x, dn, bb.x), 0.f);
    r.y = fmaxf(fmaf(acc.y, dn, bb.y), 0.f);
    r.z = fmaxf(fmaf(acc.z, dn, bb.z), 0.f);
    r.w = fmaxf(fmaf(acc.w, dn, bb.w), 0.f);
    ((float4*)(g_h + (size_t)wid * D))[lane] = r;
}

// ---------------------------------------------------------------------------
// mean pool per graph + linear head + log_softmax. one block per graph.
__global__ void k_pool(const void* __restrict__ batch,
                       const float* __restrict__ lin_w,
                       const float* __restrict__ lin_b,
                       float* hG_out, float* log_out,
                       int N, int nc) {
    int g = blockIdx.x, t = threadIdx.x;
    __shared__ int bounds[2];
    __shared__ float sh[D];
    __shared__ float sl[32];
    int is64 = g_b64;
    if (t == 0) {
        int lo = 0, hi = N;
        while (lo < hi) { int mid = (lo + hi) >> 1; if (idx_at(batch, mid, is64) < g) lo = mid + 1; else hi = mid; }
        bounds[0] = lo;
        hi = N;
        while (lo < hi) { int mid = (lo + hi) >> 1; if (idx_at(batch, mid, is64) <= g) lo = mid + 1; else hi = mid; }
        bounds[1] = lo;
    }
    __syncthreads();
    int beg = bounds[0], end = bounds[1];
    float sum = 0.f;
    for (int i = beg; i < end; i++) sum += g_h[(size_t)i * D + t];
    int c = end - beg;
    float cnt = (float)(c > 1 ? c : 1);
    float m = sum / cnt;
    if (hG_out) hG_out[(size_t)g * D + t] = m;
    sh[t] = m;
    __syncthreads();
    if (log_out) {
        if (t < nc) {
            float acc = lin_b[t];
            for (int k = 0; k < D; k++) acc += sh[k] * lin_w[k * nc + t];
            sl[t] = acc;
        }
        __syncthreads();
        if (t == 0) {
            float mx = -1e30f;
            for (int j = 0; j < nc; j++) mx = fmaxf(mx, sl[j]);
            float se = 0.f;
            for (int j = 0; j < nc; j++) se += expf(sl[j] - mx);
            float lse = mx + logf(se);
            for (int j = 0; j < nc; j++) log_out[(size_t)g * nc + j] = sl[j] - lse;
        }
    }
}

// ---------------------------------------------------------------------------
extern "C" void kernel_launch(void* const* d_in, const int* in_sizes, int n_in,
                              void* d_out, int out_size) {
    // Identify inputs by (distinct) element counts; fall back to position.
    const float* x = (const float*)d_in[0];
    const float* W = (const float*)d_in[1];
    const float* b = (const float*)d_in[2];
    const float* lin_w = (const float*)d_in[3];
    const float* lin_b = (const float*)d_in[4];
    const void* ei = d_in[5];
    const void* batch = d_in[6];
    int sz_x = in_sizes[0], sz_W = in_sizes[1], sz_lb = in_sizes[4],
        sz_ei = in_sizes[5], sz_batch = in_sizes[6];
    for (int i = 0; i < n_in; i++) {
        int s = in_sizes[i];
        switch (s) {
            case 6400000: x = (const float*)d_in[i]; sz_x = s; break;       // N*D
            case 49152:   W = (const float*)d_in[i]; sz_W = s; break;       // L*D*D
            case 384:     b = (const float*)d_in[i]; break;                 // L*D
            case 1280:    lin_w = (const float*)d_in[i]; break;             // D*nc
            case 10:      lin_b = (const float*)d_in[i]; sz_lb = s; break;  // nc
            case 1600000: ei = d_in[i]; sz_ei = s; break;                   // 2*E
            case 50000:   batch = d_in[i]; sz_batch = s; break;             // N
            default: break;
        }
    }

    int N = sz_x / D;
    int E = sz_ei / 2;
    int L = sz_W / (D * D);
    int nc = sz_lb;

    float* out = (float*)d_out;
    float* hG_out = 0;
    float* log_out = 0;
    int G = 0;
    if (out_size % (D + nc) == 0) {     // concatenated (hG, log_softmax)
        G = out_size / (D + nc);
        hG_out = out;
        log_out = out + (size_t)G * D;
    } else if (out_size % D == 0) {     // hG only
        G = out_size / D;
        hG_out = out;
    } else {                            // logits only
        G = out_size / nc;
        log_out = out;
    }

    int tE = (E + 255) / 256;
    int tN = (N + 255) / 256;
    int gemm_blocks = (N + 127) / 128;
    int agg_blocks = (N + 7) / 8;       // 8 warps/block, warp per node

    // launch order puts gemm1 at position 6 so ncu (-s 5 -c 1) profiles it
    k_zero_deg<<<tN, 256>>>(N);                              // 1
    k_detect2<<<32, 256>>>(ei, sz_ei, N, batch, sz_batch, G);// 2
    k_count<<<tE, 256>>>(ei, E, N);                          // 3
    k_scan<<<1, 1024>>>(N, E);                               // 4
    k_scatter<<<tE, 256>>>(ei, E, N);                        // 5
    for (int l = 0; l < L; l++) {
        k_gemm<<<gemm_blocks, 256>>>(x, W + (size_t)l * D * D, N, l == 0 ? 1 : 0);
        k_agg<<<agg_blocks, 256>>>(b + (size_t)l * D, N, E);
    }
    k_pool<<<G, D>>>(batch, lin_w, lin_b, hG_out, log_out, N, nc);
}